// round 15
// baseline (speedup 1.0000x reference)
#include <cuda_runtime.h>
#include <cuda_fp16.h>
#include <cstdint>

#define B_ 2048
#define E_ 256
#define H_ 1024
#define V_ 42
#define S_ 100
#define XP 64            // padded x width (42 -> 64 halves = 2 full k32 chunks)

// ---------------- persistent device state (fp16 activations, fp32 cell) -----
__device__ __half g_x[B_ * XP];
__device__ __half g_h0[2][B_ * H_];
__device__ __half g_h1[2][B_ * H_];
__device__ float g_c0[B_ * H_];
__device__ float g_c1[B_ * H_];
__device__ __half g_whh0t[4 * H_ * H_];
__device__ __half g_wih0t[4 * H_ * XP];   // zero-padded cols 42..63
__device__ __half g_whh1t[4 * H_ * H_];
__device__ __half g_wih1t[4 * H_ * H_];
__device__ float g_fc2t[H_ * 48];         // fc2_w transposed [k][v], v padded to 48

// ---------------- helpers ---------------------------------------------------
__device__ __forceinline__ float fsigm(float x) {
    return __fdividef(1.f, 1.f + __expf(-x));
}
__device__ __forceinline__ float ftanh(float x) {
    return __fdividef(2.f, 1.f + __expf(-2.f * x)) - 1.f;
}

// ---------------- prep + init (single launch) -------------------------------
__global__ void prep_all(const float* __restrict__ whh0, const float* __restrict__ wih0,
                         const float* __restrict__ whh1, const float* __restrict__ wih1,
                         const float* __restrict__ fc2w)
{
    const int nHH = 4 * H_ * H_;
    const int nIH0 = 4 * H_ * XP;
    const int nBH = B_ * H_;
    const int nBX = B_ * XP;
    const int nF = H_ * 48;
    int i = blockIdx.x * blockDim.x + threadIdx.x;
    if (i < nHH) {
        g_whh0t[i] = __float2half_rn(whh0[i]);
    } else if (i < 2 * nHH) {
        g_whh1t[i - nHH] = __float2half_rn(whh1[i - nHH]);
    } else if (i < 3 * nHH) {
        g_wih1t[i - 2 * nHH] = __float2half_rn(wih1[i - 2 * nHH]);
    } else if (i < 3 * nHH + nIH0) {
        int j = i - 3 * nHH;
        int r = j >> 6, k = j & 63;
        g_wih0t[j] = (k < V_) ? __float2half_rn(wih0[r * V_ + k]) : __float2half_rn(0.f);
    } else if (i < 3 * nHH + nIH0 + nBH) {
        int j = i - 3 * nHH - nIH0;
        g_c0[j] = 0.f; g_c1[j] = 0.f;
        g_h1[0][j] = __float2half_rn(0.f);
    } else if (i < 3 * nHH + nIH0 + nBH + nBX) {
        int j = i - 3 * nHH - nIH0 - nBH;
        g_x[j] = __float2half_rn(((j & 63) == V_ - 1) ? 1.f : 0.f);
    } else if (i < 3 * nHH + nIH0 + nBH + nBX + nF) {
        int j = i - 3 * nHH - nIH0 - nBH - nBX;
        int k = j / 48, v = j - k * 48;
        g_fc2t[j] = (v < V_) ? fc2w[(size_t)v * H_ + k] : 0.f;
    }
}

// ---------------- fc1: h0 = latent @ fc1_w^T + b (one-time, fp32 math) ------
__global__ __launch_bounds__(256) void fc1_kernel(
    const float* __restrict__ latent, const float* __restrict__ w,
    const float* __restrict__ bias)
{
    __shared__ float As[16][68];
    __shared__ float Ws[16][68];
    const int tid = threadIdx.x;
    const int bm = blockIdx.y * 64, bn = blockIdx.x * 64;
    const int r = tid >> 2, kq = (tid & 3) * 4;
    const int tx = tid & 15, ty = tid >> 4;
    float acc[4][4];
#pragma unroll
    for (int i = 0; i < 4; i++)
#pragma unroll
        for (int j = 0; j < 4; j++) acc[i][j] = 0.f;
    for (int k0 = 0; k0 < E_; k0 += 16) {
        float4 av = *reinterpret_cast<const float4*>(latent + (size_t)(bm + r) * E_ + k0 + kq);
        float4 wv = *reinterpret_cast<const float4*>(w + (size_t)(bn + r) * E_ + k0 + kq);
        __syncthreads();
        As[kq + 0][r] = av.x; As[kq + 1][r] = av.y; As[kq + 2][r] = av.z; As[kq + 3][r] = av.w;
        Ws[kq + 0][r] = wv.x; Ws[kq + 1][r] = wv.y; Ws[kq + 2][r] = wv.z; Ws[kq + 3][r] = wv.w;
        __syncthreads();
#pragma unroll
        for (int kk = 0; kk < 16; kk++) {
            float4 a = *(const float4*)&As[kk][ty * 4];
            float4 b = *(const float4*)&Ws[kk][tx * 4];
            float am[4] = {a.x, a.y, a.z, a.w};
            float bn2[4] = {b.x, b.y, b.z, b.w};
#pragma unroll
            for (int mi = 0; mi < 4; mi++)
#pragma unroll
                for (int ni = 0; ni < 4; ni++)
                    acc[mi][ni] = fmaf(am[mi], bn2[ni], acc[mi][ni]);
        }
    }
#pragma unroll
    for (int mi = 0; mi < 4; mi++) {
        int m = bm + ty * 4 + mi;
#pragma unroll
        for (int ni = 0; ni < 4; ni++)
            g_h0[0][(size_t)m * H_ + bn + tx * 4 + ni] =
                __float2half_rn(acc[mi][ni] + bias[bn + tx * 4 + ni]);
    }
}

// ---------------- FP16 tensor-core gates GEMM + fused LSTM cell --------------
// CTA tile 256m x 128j (j = nl*4 + g), 512 threads, 16 warps of 64m x 32j.
// At the legacy mma.sync dispatch ceiling (~190 TF/s); this round halves the
// barrier count: 6-stage k32 ring, one wait+__syncthreads per TWO chunks.
#define NSTG 6
#define AS_STRIDE 40                      // halves; 80B rows -> conflict-free LDSM
#define A_STG (256 * AS_STRIDE)           // halves per A stage
#define B_STG (128 * AS_STRIDE)           // halves per B stage

template <int K2P, int LAYER>
__global__ __launch_bounds__(512, 1) void gates_mma(
    int p,
    const __half* __restrict__ W1,    // w_hh fp16 [4H, H]
    const __half* __restrict__ W2,    // w_ih fp16 [4H, K2P]
    const float* __restrict__ bih,
    const float* __restrict__ bhh)
{
    constexpr int T1 = H_ / 32;       // 32 k32-chunks from hh
    constexpr int T2 = K2P / 32;      // 2 (layer0) or 32 (layer1)
    constexpr int T = T1 + T2;        // even for both layers
    constexpr int PT = T / 2;         // barrier iterations (chunk pairs)

    const __half* A1;
    const __half* A2;
    float* cbuf;
    __half* hout;
    if (LAYER == 0) { A1 = g_h0[p]; A2 = g_x;         cbuf = g_c0; hout = g_h0[p ^ 1]; }
    else            { A1 = g_h1[p]; A2 = g_h0[p ^ 1]; cbuf = g_c1; hout = g_h1[p ^ 1]; }
    const int strideA2 = (LAYER == 0) ? XP : H_;

    extern __shared__ __half sm[];
    __half (*As)[256][AS_STRIDE] = reinterpret_cast<__half (*)[256][AS_STRIDE]>(sm);
    __half (*Bs)[128][AS_STRIDE] =
        reinterpret_cast<__half (*)[128][AS_STRIDE]>(sm + NSTG * A_STG);

    const int tid = threadIdx.x;
    const int bm = blockIdx.y * 256;
    const int bn = blockIdx.x * 32;

    // ---- loader: A = all 512 threads (2 ops), B = threads < 256 (2 ops) ----
    const int arow = tid >> 1;            // 0..255
    const int akq = (tid & 1) * 16;       // halves: 0 or 16
    const __half* aRow1 = A1 + (size_t)(bm + arow) * H_;
    const __half* aRow2 = A2 + (size_t)(bm + arow) * strideA2;
    const int brow = (tid & 255) >> 1;    // 0..127 (valid when tid < 256)
    const int bkq = (tid & 1) * 16;
    const int wrow = (brow & 3) * H_ + bn + (brow >> 2);   // j = nl*4+g
    const __half* bRow1 = W1 + (size_t)wrow * H_;
    const __half* bRow2 = W2 + (size_t)wrow * K2P;

    auto issue = [&](int kt) {
        const int buf = kt % NSTG;
        const __half* as;
        const __half* bs;
        if (kt < T1) { int k = kt * 32;        as = aRow1 + k + akq; bs = bRow1 + k + bkq; }
        else         { int k = (kt - T1) * 32; as = aRow2 + k + akq; bs = bRow2 + k + bkq; }
        uint32_t da = (uint32_t)__cvta_generic_to_shared(&As[buf][arow][akq]);
        asm volatile(
            "cp.async.cg.shared.global [%0], [%1], 16;\n\t"
            "cp.async.cg.shared.global [%2], [%3], 16;\n\t"
            :: "r"(da), "l"(as), "r"(da + 16), "l"(as + 8) : "memory");
        if (tid < 256) {
            uint32_t db = (uint32_t)__cvta_generic_to_shared(&Bs[buf][brow][bkq]);
            asm volatile(
                "cp.async.cg.shared.global [%0], [%1], 16;\n\t"
                "cp.async.cg.shared.global [%2], [%3], 16;\n\t"
                :: "r"(db), "l"(bs), "r"(db + 16), "l"(bs + 8) : "memory");
        }
        asm volatile("cp.async.commit_group;" ::: "memory");
    };

    // ---- mma mapping: 16 warps, warp tile 64m x 32j ----
    const int lane = tid & 31;
    const int wid = tid >> 5;
    const int wm = wid & 3;               // 4 warp-rows over m (64 each)
    const int wj = wid >> 2;              // 4 warp-cols over j (32 each)
    const int gid = lane >> 2, tig = lane & 3;

    // ---- ldmatrix base addresses (stage/sub-k offsets added in loop) ----
    const int lmat = lane >> 3, lrow8 = lane & 7;
    const uint32_t as_base = (uint32_t)__cvta_generic_to_shared(&As[0][0][0]);
    const uint32_t bs_base = (uint32_t)__cvta_generic_to_shared(&Bs[0][0][0]);
    uint32_t aAddr[4], bAddr[2];
#pragma unroll
    for (int mt = 0; mt < 4; mt++) {
        // x4 matrices: 0:(m0-7,k0-7) 1:(m8-15,k0-7) 2:(m0-7,k8-15) 3:(m8-15,k8-15)
        const int row = wm * 64 + mt * 16 + (lmat & 1) * 8 + lrow8;
        const int col = (lmat >> 1) * 8;
        aAddr[mt] = as_base + (uint32_t)(row * AS_STRIDE + col) * 2;
    }
#pragma unroll
    for (int g = 0; g < 2; g++) {
        // x4 matrices: 0:(j0-7,k0-7) 1:(j0-7,k8-15) 2:(j8-15,k0-7) 3:(j8-15,k8-15)
        const int row = wj * 32 + g * 16 + (lmat >> 1) * 8 + lrow8;
        const int col = (lmat & 1) * 8;
        bAddr[g] = bs_base + (uint32_t)(row * AS_STRIDE + col) * 2;
    }

    float acc[4][4][4];
#pragma unroll
    for (int a = 0; a < 4; a++)
#pragma unroll
        for (int b = 0; b < 4; b++)
#pragma unroll
            for (int c = 0; c < 4; c++) acc[a][b][c] = 0.f;

    issue(0);
    issue(1);
    issue(2);
    issue(3);

    for (int i = 0; i < PT; ++i) {
        if (2 * i + 4 < T) {
            asm volatile("cp.async.wait_group 2;" ::: "memory");
            __syncthreads();
            issue(2 * i + 4);
            issue(2 * i + 5);
        } else if (i == PT - 2) {
            asm volatile("cp.async.wait_group 2;" ::: "memory");
            __syncthreads();
        } else {  // i == PT - 1
            asm volatile("cp.async.wait_group 0;" ::: "memory");
            __syncthreads();
        }
#pragma unroll
        for (int cc = 0; cc < 2; ++cc) {            // two k32 chunks per barrier
            const int kt = 2 * i + cc;
            const int buf = kt % NSTG;
            const uint32_t soA = (uint32_t)buf * (uint32_t)(A_STG * 2);
            const uint32_t soB = (uint32_t)buf * (uint32_t)(B_STG * 2);
#pragma unroll
            for (int h = 0; h < 2; h++) {           // two k16 sub-tiles per chunk
                const uint32_t ho = (uint32_t)h * 32;   // +16 halves
                uint32_t a[4][4], b[4][2];
#pragma unroll
                for (int mt = 0; mt < 4; mt++)
                    asm volatile(
                        "ldmatrix.sync.aligned.m8n8.x4.shared.b16 {%0,%1,%2,%3}, [%4];"
                        : "=r"(a[mt][0]), "=r"(a[mt][1]), "=r"(a[mt][2]), "=r"(a[mt][3])
                        : "r"(aAddr[mt] + soA + ho));
#pragma unroll
                for (int g = 0; g < 2; g++)
                    asm volatile(
                        "ldmatrix.sync.aligned.m8n8.x4.shared.b16 {%0,%1,%2,%3}, [%4];"
                        : "=r"(b[2 * g][0]), "=r"(b[2 * g][1]),
                          "=r"(b[2 * g + 1][0]), "=r"(b[2 * g + 1][1])
                        : "r"(bAddr[g] + soB + ho));
#pragma unroll
                for (int mt = 0; mt < 4; mt++)
#pragma unroll
                    for (int nt = 0; nt < 4; nt++)
                        asm volatile(
                            "mma.sync.aligned.m16n8k16.row.col.f32.f16.f16.f32 "
                            "{%0,%1,%2,%3}, {%4,%5,%6,%7}, {%8,%9}, {%0,%1,%2,%3};"
                            : "+f"(acc[mt][nt][0]), "+f"(acc[mt][nt][1]),
                              "+f"(acc[mt][nt][2]), "+f"(acc[mt][nt][3])
                            : "r"(a[mt][0]), "r"(a[mt][1]), "r"(a[mt][2]), "r"(a[mt][3]),
                              "r"(b[nt][0]), "r"(b[nt][1]));
            }
        }
    }

    // ---- fused LSTM cell epilogue via lane-pair shuffle (verified) ----
    const bool isA = (tig & 1) == 0;
    const int gl = (tig & 1) * 2;
#pragma unroll
    for (int nt = 0; nt < 4; nt++) {
        const int col = bn + wj * 8 + nt * 2 + (tig >> 1);
        const float bias0 = bih[gl * H_ + col] + bhh[gl * H_ + col];
        const float bias1 = bih[(gl + 1) * H_ + col] + bhh[(gl + 1) * H_ + col];
#pragma unroll
        for (int mt = 0; mt < 4; mt++) {
#pragma unroll
            for (int rh = 0; rh < 2; rh++) {
                const int m = bm + wm * 64 + mt * 16 + gid + rh * 8;
                const size_t off = (size_t)m * H_ + col;
                const float p0 = acc[mt][nt][rh * 2 + 0] + bias0;  // A: i, B: g
                const float p1 = acc[mt][nt][rh * 2 + 1] + bias1;  // A: f, B: o
                const float e = __expf(isA ? -p0 : -2.f * p0);
                const float q0 = __fdividef(isA ? 1.f : 2.f, 1.f + e) - (isA ? 0.f : 1.f);
                const float q1 = fsigm(p1);                        // A: sig(f), B: sig(o)
                const float partner = __shfl_xor_sync(0xffffffffu, q0, 1); // A: tanh(g)
                const float cold = isA ? cbuf[off] : 0.f;
                const float cn = fmaf(q1, cold, q0 * partner);     // A: sf*c + si*tg
                const float th = ftanh(cn);
                const float th2 = __shfl_xor_sync(0xffffffffu, th, 1);     // B: tanh(cn)
                if (isA) cbuf[off] = cn;
                else     hout[off] = __float2half_rn(q1 * th2);    // B: sig(o)*tanh(cn)
            }
        }
    }
}

// ---------------- logits + softmax feedback (3-stage cp.async pipeline) ------
#define LB 16
#define KC 64
#define LT (H_ / KC)                      // 16 k-iterations
__global__ __launch_bounds__(256) void logits_kernel(
    int p, int t,
    const float* __restrict__ bias,
    float* __restrict__ out)
{
    const __half* h = g_h1[p ^ 1];
    __shared__ __half hs[3][LB][72];      // 144B rows, 16B-aligned chunks
    __shared__ float ws[3][KC][48];       // transposed fc2 tile, coalesced
    __shared__ float ls[LB][48];
    const int tid = threadIdx.x;
    const int b0 = blockIdx.x * LB;
    const int r = tid >> 4, q = tid & 15;

    auto issue = [&](int it) {
        const int s = it % 3;
        const int k0 = it * KC;
        if (tid < 128) {
            const int rr = tid >> 3, c = tid & 7;
            uint32_t dst = (uint32_t)__cvta_generic_to_shared(&hs[s][rr][c * 8]);
            const __half* src = h + (size_t)(b0 + rr) * H_ + k0 + c * 8;
            asm volatile("cp.async.ca.shared.global [%0], [%1], 16;"
                         :: "r"(dst), "l"(src) : "memory");
        }
#pragma unroll
        for (int i = 0; i < 3; i++) {
            const int id = tid + i * 256;       // 0..767 = 64 rows x 12 chunks
            const int kk = id / 12, c = id - kk * 12;
            uint32_t dst = (uint32_t)__cvta_generic_to_shared(&ws[s][kk][c * 4]);
            const float* src = g_fc2t + (size_t)(k0 + kk) * 48 + c * 4;
            asm volatile("cp.async.ca.shared.global [%0], [%1], 16;"
                         :: "r"(dst), "l"(src) : "memory");
        }
        asm volatile("cp.async.commit_group;" ::: "memory");
    };

    float acc0 = 0.f, acc1 = 0.f, acc2 = 0.f;
    issue(0);
    issue(1);
    for (int it = 0; it < LT; ++it) {
        if (it + 2 < LT) {
            asm volatile("cp.async.wait_group 1;" ::: "memory");
            __syncthreads();
            issue(it + 2);
        } else if (it == LT - 2) {
            asm volatile("cp.async.wait_group 1;" ::: "memory");
            __syncthreads();
        } else {
            asm volatile("cp.async.wait_group 0;" ::: "memory");
            __syncthreads();
        }
        const int s = it % 3;
#pragma unroll
        for (int kk = 0; kk < KC; kk++) {
            const float a = __half2float(hs[s][r][kk]);
            acc0 = fmaf(a, ws[s][kk][q], acc0);
            acc1 = fmaf(a, ws[s][kk][q + 16], acc1);
            acc2 = fmaf(a, ws[s][kk][q + 32], acc2);   // pad cols are 0
        }
    }
    const int b = b0 + r;
    const size_t ob = (size_t)b * S_ * V_ + (size_t)t * V_;
    float l0 = acc0 + bias[q];
    float l1 = acc1 + bias[q + 16];
    ls[r][q] = l0;      out[ob + q] = l0;
    ls[r][q + 16] = l1; out[ob + q + 16] = l1;
    if (q + 32 < V_) {
        float l2 = acc2 + bias[q + 32];
        ls[r][q + 32] = l2;
        out[ob + q + 32] = l2;
    }
    __syncthreads();
    if (tid < LB) {
        float mx = -1e30f;
#pragma unroll
        for (int v = 0; v < V_; v++) mx = fmaxf(mx, ls[tid][v]);
        float ev[V_];
        float sum = 0.f;
#pragma unroll
        for (int v = 0; v < V_; v++) {
            ev[v] = __expf(ls[tid][v] - mx);
            sum += ev[v];
        }
        float inv = __fdividef(1.f, sum);
        const int bb = b0 + tid;
#pragma unroll
        for (int v = 0; v < V_; v++)
            g_x[(size_t)bb * XP + v] = __float2half_rn(ev[v] * inv);
    }
}

// ---------------- driver ----------------------------------------------------
extern "C" void kernel_launch(void* const* d_in, const int* in_sizes, int n_in,
                              void* d_out, int out_size)
{
    const float* latent = (const float*)d_in[0];
    const float* fc1_w  = (const float*)d_in[1];
    const float* fc1_b  = (const float*)d_in[2];
    const float* fc2_w  = (const float*)d_in[3];
    const float* fc2_b  = (const float*)d_in[4];
    const float* w_ih0  = (const float*)d_in[5];
    const float* w_hh0  = (const float*)d_in[6];
    const float* b_ih0  = (const float*)d_in[7];
    const float* b_hh0  = (const float*)d_in[8];
    const float* w_ih1  = (const float*)d_in[9];
    const float* w_hh1  = (const float*)d_in[10];
    const float* b_ih1  = (const float*)d_in[11];
    const float* b_hh1  = (const float*)d_in[12];
    float* out = (float*)d_out;

    __half* whh0t; cudaGetSymbolAddress((void**)&whh0t, g_whh0t);
    __half* wih0t; cudaGetSymbolAddress((void**)&wih0t, g_wih0t);
    __half* whh1t; cudaGetSymbolAddress((void**)&whh1t, g_whh1t);
    __half* wih1t; cudaGetSymbolAddress((void**)&wih1t, g_wih1t);

    const int smem_bytes = NSTG * (A_STG + B_STG) * (int)sizeof(__half);  // 184,320 B
    cudaFuncSetAttribute(gates_mma<XP, 0>,
                         cudaFuncAttributeMaxDynamicSharedMemorySize, smem_bytes);
    cudaFuncSetAttribute(gates_mma<H_, 1>,
                         cudaFuncAttributeMaxDynamicSharedMemorySize, smem_bytes);

    const int nTot = 3 * 4 * H_ * H_ + 4 * H_ * XP + B_ * H_ + B_ * XP + H_ * 48;
    // launch #4 of the run must be gates_mma<H_,1> (ncu capture slot)
    prep_all<<<(nTot + 255) / 256, 256>>>(w_hh0, w_ih0, w_hh1, w_ih1, fc2_w); // 1
    fc1_kernel<<<dim3(H_ / 64, B_ / 64), 256>>>(latent, fc1_w, fc1_b);        // 2

    for (int t = 0; t < S_; ++t) {
        const int p = t & 1;
        gates_mma<XP, 0><<<dim3(H_ / 32, B_ / 256), 512, smem_bytes>>>(
            p, whh0t, wih0t, b_ih0, b_hh0);                                   // 3
        gates_mma<H_, 1><<<dim3(H_ / 32, B_ / 256), 512, smem_bytes>>>(
            p, whh1t, wih1t, b_ih1, b_hh1);                                   // 4 <- ncu
        logits_kernel<<<B_ / LB, 256>>>(p, t, fc2_b, out);
    }
}

// round 16
// speedup vs baseline: 1.0668x; 1.0668x over previous
#include <cuda_runtime.h>
#include <cuda_fp16.h>
#include <cstdint>

#define B_ 2048
#define E_ 256
#define H_ 1024
#define V_ 42
#define S_ 100
#define XP 64            // padded x width (42 -> 64 halves = 2 full k32 chunks)

// ---------------- persistent device state (fp16 activations, fp32 cell) -----
__device__ __half g_x[B_ * XP];
__device__ __half g_h0[2][B_ * H_];
__device__ __half g_h1[2][B_ * H_];
__device__ float g_c0[B_ * H_];
__device__ float g_c1[B_ * H_];
__device__ __half g_whh0t[4 * H_ * H_];
__device__ __half g_wih0t[4 * H_ * XP];   // zero-padded cols 42..63
__device__ __half g_whh1t[4 * H_ * H_];
__device__ __half g_wih1t[4 * H_ * H_];
__device__ float g_fc2t[H_ * 48];         // fc2_w transposed [k][v], v padded to 48

// ---------------- helpers ---------------------------------------------------
__device__ __forceinline__ float fsigm(float x) {
    return __fdividef(1.f, 1.f + __expf(-x));
}
__device__ __forceinline__ float ftanh(float x) {
    return __fdividef(2.f, 1.f + __expf(-2.f * x)) - 1.f;
}

// ---------------- prep + init (single launch) -------------------------------
__global__ void prep_all(const float* __restrict__ whh0, const float* __restrict__ wih0,
                         const float* __restrict__ whh1, const float* __restrict__ wih1,
                         const float* __restrict__ fc2w)
{
    const int nHH = 4 * H_ * H_;
    const int nIH0 = 4 * H_ * XP;
    const int nBH = B_ * H_;
    const int nBX = B_ * XP;
    const int nF = H_ * 48;
    int i = blockIdx.x * blockDim.x + threadIdx.x;
    if (i < nHH) {
        g_whh0t[i] = __float2half_rn(whh0[i]);
    } else if (i < 2 * nHH) {
        g_whh1t[i - nHH] = __float2half_rn(whh1[i - nHH]);
    } else if (i < 3 * nHH) {
        g_wih1t[i - 2 * nHH] = __float2half_rn(wih1[i - 2 * nHH]);
    } else if (i < 3 * nHH + nIH0) {
        int j = i - 3 * nHH;
        int r = j >> 6, k = j & 63;
        g_wih0t[j] = (k < V_) ? __float2half_rn(wih0[r * V_ + k]) : __float2half_rn(0.f);
    } else if (i < 3 * nHH + nIH0 + nBH) {
        int j = i - 3 * nHH - nIH0;
        g_c0[j] = 0.f; g_c1[j] = 0.f;
        g_h1[0][j] = __float2half_rn(0.f);
    } else if (i < 3 * nHH + nIH0 + nBH + nBX) {
        int j = i - 3 * nHH - nIH0 - nBH;
        g_x[j] = __float2half_rn(((j & 63) == V_ - 1) ? 1.f : 0.f);
    } else if (i < 3 * nHH + nIH0 + nBH + nBX + nF) {
        int j = i - 3 * nHH - nIH0 - nBH - nBX;
        int k = j / 48, v = j - k * 48;
        g_fc2t[j] = (v < V_) ? fc2w[(size_t)v * H_ + k] : 0.f;
    }
}

// ---------------- fc1: h0 = latent @ fc1_w^T + b (one-time, fp32 math) ------
__global__ __launch_bounds__(256) void fc1_kernel(
    const float* __restrict__ latent, const float* __restrict__ w,
    const float* __restrict__ bias)
{
    __shared__ float As[16][68];
    __shared__ float Ws[16][68];
    const int tid = threadIdx.x;
    const int bm = blockIdx.y * 64, bn = blockIdx.x * 64;
    const int r = tid >> 2, kq = (tid & 3) * 4;
    const int tx = tid & 15, ty = tid >> 4;
    float acc[4][4];
#pragma unroll
    for (int i = 0; i < 4; i++)
#pragma unroll
        for (int j = 0; j < 4; j++) acc[i][j] = 0.f;
    for (int k0 = 0; k0 < E_; k0 += 16) {
        float4 av = *reinterpret_cast<const float4*>(latent + (size_t)(bm + r) * E_ + k0 + kq);
        float4 wv = *reinterpret_cast<const float4*>(w + (size_t)(bn + r) * E_ + k0 + kq);
        __syncthreads();
        As[kq + 0][r] = av.x; As[kq + 1][r] = av.y; As[kq + 2][r] = av.z; As[kq + 3][r] = av.w;
        Ws[kq + 0][r] = wv.x; Ws[kq + 1][r] = wv.y; Ws[kq + 2][r] = wv.z; Ws[kq + 3][r] = wv.w;
        __syncthreads();
#pragma unroll
        for (int kk = 0; kk < 16; kk++) {
            float4 a = *(const float4*)&As[kk][ty * 4];
            float4 b = *(const float4*)&Ws[kk][tx * 4];
            float am[4] = {a.x, a.y, a.z, a.w};
            float bn2[4] = {b.x, b.y, b.z, b.w};
#pragma unroll
            for (int mi = 0; mi < 4; mi++)
#pragma unroll
                for (int ni = 0; ni < 4; ni++)
                    acc[mi][ni] = fmaf(am[mi], bn2[ni], acc[mi][ni]);
        }
    }
#pragma unroll
    for (int mi = 0; mi < 4; mi++) {
        int m = bm + ty * 4 + mi;
#pragma unroll
        for (int ni = 0; ni < 4; ni++)
            g_h0[0][(size_t)m * H_ + bn + tx * 4 + ni] =
                __float2half_rn(acc[mi][ni] + bias[bn + tx * 4 + ni]);
    }
}

// ---------------- FP16 tensor-core gates GEMM + fused LSTM cell --------------
// OCCUPANCY EXPERIMENT: warp tile 32m x 32j (32 accums, ~80 regs), CTA 64m x
// 128j with 256 threads, 3 CTAs/SM -> 24 warps/SM (was register-capped at 16).
#define NSTG 4
#define AS_STRIDE 40                      // halves; 80B rows -> conflict-free LDSM
#define A_STG (64 * AS_STRIDE)            // halves per A stage
#define B_STG (128 * AS_STRIDE)           // halves per B stage

template <int K2P, int LAYER>
__global__ __launch_bounds__(256, 3) void gates_mma(
    int p,
    const __half* __restrict__ W1,    // w_hh fp16 [4H, H]
    const __half* __restrict__ W2,    // w_ih fp16 [4H, K2P]
    const float* __restrict__ bih,
    const float* __restrict__ bhh)
{
    constexpr int T1 = H_ / 32;       // 32 k32-chunks from hh
    constexpr int T2 = K2P / 32;      // 2 (layer0) or 32 (layer1)
    constexpr int T = T1 + T2;

    const __half* A1;
    const __half* A2;
    float* cbuf;
    __half* hout;
    if (LAYER == 0) { A1 = g_h0[p]; A2 = g_x;         cbuf = g_c0; hout = g_h0[p ^ 1]; }
    else            { A1 = g_h1[p]; A2 = g_h0[p ^ 1]; cbuf = g_c1; hout = g_h1[p ^ 1]; }
    const int strideA2 = (LAYER == 0) ? XP : H_;

    extern __shared__ __half sm[];
    __half (*As)[64][AS_STRIDE] = reinterpret_cast<__half (*)[64][AS_STRIDE]>(sm);
    __half (*Bs)[128][AS_STRIDE] =
        reinterpret_cast<__half (*)[128][AS_STRIDE]>(sm + NSTG * A_STG);

    const int tid = threadIdx.x;
    const int bm = blockIdx.y * 64;
    const int bn = blockIdx.x * 32;

    // ---- loader: A = 1 op/thread (64 rows x 4 segs), B = 2 ops/thread ----
    const int arow = tid >> 2;            // 0..63
    const int aseg = (tid & 3) * 8;       // halves: 0,8,16,24
    const __half* aRow1 = A1 + (size_t)(bm + arow) * H_;
    const __half* aRow2 = A2 + (size_t)(bm + arow) * strideA2;
    const int brow = tid >> 1;            // 0..127
    const int bkq = (tid & 1) * 16;       // halves: 0 or 16
    const int wrow = (brow & 3) * H_ + bn + (brow >> 2);   // j = nl*4+g
    const __half* bRow1 = W1 + (size_t)wrow * H_;
    const __half* bRow2 = W2 + (size_t)wrow * K2P;

    auto issue = [&](int kt) {
        const int buf = kt & (NSTG - 1);
        const __half* as;
        const __half* bs;
        if (kt < T1) { int k = kt * 32;        as = aRow1 + k; bs = bRow1 + k; }
        else         { int k = (kt - T1) * 32; as = aRow2 + k; bs = bRow2 + k; }
        uint32_t da = (uint32_t)__cvta_generic_to_shared(&As[buf][arow][aseg]);
        asm volatile("cp.async.cg.shared.global [%0], [%1], 16;"
                     :: "r"(da), "l"(as + aseg) : "memory");
        uint32_t db = (uint32_t)__cvta_generic_to_shared(&Bs[buf][brow][bkq]);
        asm volatile(
            "cp.async.cg.shared.global [%0], [%1], 16;\n\t"
            "cp.async.cg.shared.global [%2], [%3], 16;\n\t"
            "cp.async.commit_group;\n\t"
            :: "r"(db), "l"(bs + bkq), "r"(db + 16), "l"(bs + bkq + 8) : "memory");
    };

    // ---- mma mapping: 8 warps, warp tile 32m x 32j (wm 2 x wj 4) ----
    const int lane = tid & 31;
    const int wid = tid >> 5;
    const int wm = wid & 1;               // 2 warp-rows over m (32 each)
    const int wj = wid >> 1;              // 4 warp-cols over j (32 each)
    const int gid = lane >> 2, tig = lane & 3;

    // ---- ldmatrix base addresses ----
    const int lmat = lane >> 3, lrow8 = lane & 7;
    const uint32_t as_base = (uint32_t)__cvta_generic_to_shared(&As[0][0][0]);
    const uint32_t bs_base = (uint32_t)__cvta_generic_to_shared(&Bs[0][0][0]);
    uint32_t aAddr[2], bAddr[2];
#pragma unroll
    for (int mt = 0; mt < 2; mt++) {
        // x4 matrices: 0:(m0-7,k0-7) 1:(m8-15,k0-7) 2:(m0-7,k8-15) 3:(m8-15,k8-15)
        const int row = wm * 32 + mt * 16 + (lmat & 1) * 8 + lrow8;
        const int col = (lmat >> 1) * 8;
        aAddr[mt] = as_base + (uint32_t)(row * AS_STRIDE + col) * 2;
    }
#pragma unroll
    for (int g = 0; g < 2; g++) {
        // x4 matrices: 0:(j0-7,k0-7) 1:(j0-7,k8-15) 2:(j8-15,k0-7) 3:(j8-15,k8-15)
        const int row = wj * 32 + g * 16 + (lmat >> 1) * 8 + lrow8;
        const int col = (lmat & 1) * 8;
        bAddr[g] = bs_base + (uint32_t)(row * AS_STRIDE + col) * 2;
    }

    float acc[2][4][4];
#pragma unroll
    for (int a = 0; a < 2; a++)
#pragma unroll
        for (int b = 0; b < 4; b++)
#pragma unroll
            for (int c = 0; c < 4; c++) acc[a][b][c] = 0.f;

    issue(0);
    issue(1);
    issue(2);

    for (int kt = 0; kt < T; ++kt) {
        const int buf = kt & (NSTG - 1);
        if (kt + 3 < T) {
            asm volatile("cp.async.wait_group 2;" ::: "memory");
            __syncthreads();
            issue(kt + 3);
        } else if (kt == T - 3) {
            asm volatile("cp.async.wait_group 2;" ::: "memory");
            __syncthreads();
        } else if (kt == T - 2) {
            asm volatile("cp.async.wait_group 1;" ::: "memory");
            __syncthreads();
        } else {
            asm volatile("cp.async.wait_group 0;" ::: "memory");
            __syncthreads();
        }
        const uint32_t soA = (uint32_t)buf * (uint32_t)(A_STG * 2);
        const uint32_t soB = (uint32_t)buf * (uint32_t)(B_STG * 2);
#pragma unroll
        for (int h = 0; h < 2; h++) {               // two k16 sub-tiles of the k32 chunk
            const uint32_t ho = (uint32_t)h * 32;   // +16 halves
            uint32_t a[2][4], b[4][2];
#pragma unroll
            for (int mt = 0; mt < 2; mt++)
                asm volatile(
                    "ldmatrix.sync.aligned.m8n8.x4.shared.b16 {%0,%1,%2,%3}, [%4];"
                    : "=r"(a[mt][0]), "=r"(a[mt][1]), "=r"(a[mt][2]), "=r"(a[mt][3])
                    : "r"(aAddr[mt] + soA + ho));
#pragma unroll
            for (int g = 0; g < 2; g++)
                asm volatile(
                    "ldmatrix.sync.aligned.m8n8.x4.shared.b16 {%0,%1,%2,%3}, [%4];"
                    : "=r"(b[2 * g][0]), "=r"(b[2 * g][1]),
                      "=r"(b[2 * g + 1][0]), "=r"(b[2 * g + 1][1])
                    : "r"(bAddr[g] + soB + ho));
#pragma unroll
            for (int mt = 0; mt < 2; mt++)
#pragma unroll
                for (int nt = 0; nt < 4; nt++)
                    asm volatile(
                        "mma.sync.aligned.m16n8k16.row.col.f32.f16.f16.f32 "
                        "{%0,%1,%2,%3}, {%4,%5,%6,%7}, {%8,%9}, {%0,%1,%2,%3};"
                        : "+f"(acc[mt][nt][0]), "+f"(acc[mt][nt][1]),
                          "+f"(acc[mt][nt][2]), "+f"(acc[mt][nt][3])
                        : "r"(a[mt][0]), "r"(a[mt][1]), "r"(a[mt][2]), "r"(a[mt][3]),
                          "r"(b[nt][0]), "r"(b[nt][1]));
        }
    }

    // ---- fused LSTM cell epilogue via lane-pair shuffle (verified) ----
    const bool isA = (tig & 1) == 0;
    const int gl = (tig & 1) * 2;
#pragma unroll
    for (int nt = 0; nt < 4; nt++) {
        const int col = bn + wj * 8 + nt * 2 + (tig >> 1);
        const float bias0 = bih[gl * H_ + col] + bhh[gl * H_ + col];
        const float bias1 = bih[(gl + 1) * H_ + col] + bhh[(gl + 1) * H_ + col];
#pragma unroll
        for (int mt = 0; mt < 2; mt++) {
#pragma unroll
            for (int rh = 0; rh < 2; rh++) {
                const int m = bm + wm * 32 + mt * 16 + gid + rh * 8;
                const size_t off = (size_t)m * H_ + col;
                const float p0 = acc[mt][nt][rh * 2 + 0] + bias0;  // A: i, B: g
                const float p1 = acc[mt][nt][rh * 2 + 1] + bias1;  // A: f, B: o
                const float e = __expf(isA ? -p0 : -2.f * p0);
                const float q0 = __fdividef(isA ? 1.f : 2.f, 1.f + e) - (isA ? 0.f : 1.f);
                const float q1 = fsigm(p1);                        // A: sig(f), B: sig(o)
                const float partner = __shfl_xor_sync(0xffffffffu, q0, 1); // A: tanh(g)
                const float cold = isA ? cbuf[off] : 0.f;
                const float cn = fmaf(q1, cold, q0 * partner);     // A: sf*c + si*tg
                const float th = ftanh(cn);
                const float th2 = __shfl_xor_sync(0xffffffffu, th, 1);     // B: tanh(cn)
                if (isA) cbuf[off] = cn;
                else     hout[off] = __float2half_rn(q1 * th2);    // B: sig(o)*tanh(cn)
            }
        }
    }
}

// ---------------- logits + softmax feedback (3-stage cp.async pipeline) ------
#define LB 16
#define KC 64
#define LT (H_ / KC)                      // 16 k-iterations
__global__ __launch_bounds__(256) void logits_kernel(
    int p, int t,
    const float* __restrict__ bias,
    float* __restrict__ out)
{
    const __half* h = g_h1[p ^ 1];
    __shared__ __half hs[3][LB][72];      // 144B rows, 16B-aligned chunks
    __shared__ float ws[3][KC][48];       // transposed fc2 tile, coalesced
    __shared__ float ls[LB][48];
    const int tid = threadIdx.x;
    const int b0 = blockIdx.x * LB;
    const int r = tid >> 4, q = tid & 15;

    auto issue = [&](int it) {
        const int s = it % 3;
        const int k0 = it * KC;
        if (tid < 128) {
            const int rr = tid >> 3, c = tid & 7;
            uint32_t dst = (uint32_t)__cvta_generic_to_shared(&hs[s][rr][c * 8]);
            const __half* src = h + (size_t)(b0 + rr) * H_ + k0 + c * 8;
            asm volatile("cp.async.ca.shared.global [%0], [%1], 16;"
                         :: "r"(dst), "l"(src) : "memory");
        }
#pragma unroll
        for (int i = 0; i < 3; i++) {
            const int id = tid + i * 256;       // 0..767 = 64 rows x 12 chunks
            const int kk = id / 12, c = id - kk * 12;
            uint32_t dst = (uint32_t)__cvta_generic_to_shared(&ws[s][kk][c * 4]);
            const float* src = g_fc2t + (size_t)(k0 + kk) * 48 + c * 4;
            asm volatile("cp.async.ca.shared.global [%0], [%1], 16;"
                         :: "r"(dst), "l"(src) : "memory");
        }
        asm volatile("cp.async.commit_group;" ::: "memory");
    };

    float acc0 = 0.f, acc1 = 0.f, acc2 = 0.f;
    issue(0);
    issue(1);
    for (int it = 0; it < LT; ++it) {
        if (it + 2 < LT) {
            asm volatile("cp.async.wait_group 1;" ::: "memory");
            __syncthreads();
            issue(it + 2);
        } else if (it == LT - 2) {
            asm volatile("cp.async.wait_group 1;" ::: "memory");
            __syncthreads();
        } else {
            asm volatile("cp.async.wait_group 0;" ::: "memory");
            __syncthreads();
        }
        const int s = it % 3;
#pragma unroll
        for (int kk = 0; kk < KC; kk++) {
            const float a = __half2float(hs[s][r][kk]);
            acc0 = fmaf(a, ws[s][kk][q], acc0);
            acc1 = fmaf(a, ws[s][kk][q + 16], acc1);
            acc2 = fmaf(a, ws[s][kk][q + 32], acc2);   // pad cols are 0
        }
    }
    const int b = b0 + r;
    const size_t ob = (size_t)b * S_ * V_ + (size_t)t * V_;
    float l0 = acc0 + bias[q];
    float l1 = acc1 + bias[q + 16];
    ls[r][q] = l0;      out[ob + q] = l0;
    ls[r][q + 16] = l1; out[ob + q + 16] = l1;
    if (q + 32 < V_) {
        float l2 = acc2 + bias[q + 32];
        ls[r][q + 32] = l2;
        out[ob + q + 32] = l2;
    }
    __syncthreads();
    if (tid < LB) {
        float mx = -1e30f;
#pragma unroll
        for (int v = 0; v < V_; v++) mx = fmaxf(mx, ls[tid][v]);
        float ev[V_];
        float sum = 0.f;
#pragma unroll
        for (int v = 0; v < V_; v++) {
            ev[v] = __expf(ls[tid][v] - mx);
            sum += ev[v];
        }
        float inv = __fdividef(1.f, sum);
        const int bb = b0 + tid;
#pragma unroll
        for (int v = 0; v < V_; v++)
            g_x[(size_t)bb * XP + v] = __float2half_rn(ev[v] * inv);
    }
}

// ---------------- driver ----------------------------------------------------
extern "C" void kernel_launch(void* const* d_in, const int* in_sizes, int n_in,
                              void* d_out, int out_size)
{
    const float* latent = (const float*)d_in[0];
    const float* fc1_w  = (const float*)d_in[1];
    const float* fc1_b  = (const float*)d_in[2];
    const float* fc2_w  = (const float*)d_in[3];
    const float* fc2_b  = (const float*)d_in[4];
    const float* w_ih0  = (const float*)d_in[5];
    const float* w_hh0  = (const float*)d_in[6];
    const float* b_ih0  = (const float*)d_in[7];
    const float* b_hh0  = (const float*)d_in[8];
    const float* w_ih1  = (const float*)d_in[9];
    const float* w_hh1  = (const float*)d_in[10];
    const float* b_ih1  = (const float*)d_in[11];
    const float* b_hh1  = (const float*)d_in[12];
    float* out = (float*)d_out;

    __half* whh0t; cudaGetSymbolAddress((void**)&whh0t, g_whh0t);
    __half* wih0t; cudaGetSymbolAddress((void**)&wih0t, g_wih0t);
    __half* whh1t; cudaGetSymbolAddress((void**)&whh1t, g_whh1t);
    __half* wih1t; cudaGetSymbolAddress((void**)&wih1t, g_wih1t);

    const int smem_bytes = NSTG * (A_STG + B_STG) * (int)sizeof(__half);  // 61,440 B
    cudaFuncSetAttribute(gates_mma<XP, 0>,
                         cudaFuncAttributeMaxDynamicSharedMemorySize, smem_bytes);
    cudaFuncSetAttribute(gates_mma<H_, 1>,
                         cudaFuncAttributeMaxDynamicSharedMemorySize, smem_bytes);

    const int nTot = 3 * 4 * H_ * H_ + 4 * H_ * XP + B_ * H_ + B_ * XP + H_ * 48;
    // launch #4 of the run must be gates_mma<H_,1> (ncu capture slot)
    prep_all<<<(nTot + 255) / 256, 256>>>(w_hh0, w_ih0, w_hh1, w_ih1, fc2_w); // 1
    fc1_kernel<<<dim3(H_ / 64, B_ / 64), 256>>>(latent, fc1_w, fc1_b);        // 2

    for (int t = 0; t < S_; ++t) {
        const int p = t & 1;
        gates_mma<XP, 0><<<dim3(H_ / 32, B_ / 64), 256, smem_bytes>>>(
            p, whh0t, wih0t, b_ih0, b_hh0);                                   // 3
        gates_mma<H_, 1><<<dim3(H_ / 32, B_ / 64), 256, smem_bytes>>>(
            p, whh1t, wih1t, b_ih1, b_hh1);                                   // 4 <- ncu
        logits_kernel<<<B_ / LB, 256>>>(p, t, fc2_b, out);
    }
}